// round 12
// baseline (speedup 1.0000x reference)
#include <cuda_runtime.h>
#include <cuda_bf16.h>
#include <cstdint>

// CPLSTM_20959440405049 — constant-folded (proof: h0=0 and the multiplicative
// gate g=(h@a)*(x_t@b) give g=0 ==> f=i=o=sigmoid(0)=0.5, g_t=tanh(0)=0 ==>
// c'=0.5*0+0.5*0=0, h'=0.5*tanh(0)=0; by induction h_t=c_t=0 exactly for all t).
// output = dec_b broadcast over (S*B, V); (c_T, h_T) = zeros. rel_err = 0.0.
//
// Round 11: five register-store configs all plateau at 6.44-6.50 TB/s
// (DRAM-write ceiling suspect). Final distinct mechanism: cp.async.bulk
// SMEM->GMEM (TMA/UTMASTG) — bypasses the SM store pipeline, emits perfectly
// sequential 32000-B bursts. Each CTA stages its 31.25KB dec_b segment in
// SMEM once, then bulk-stores it to 8 consecutive rows (12.5% staging
// overhead, L2-resident reads only).

__device__ __forceinline__ void st_v8(float* p, const float4& a, const float4& b)
{
    asm volatile(
        "st.global.v8.f32 [%0], {%1,%2,%3,%4,%5,%6,%7,%8};"
        :: "l"(p),
           "f"(a.x), "f"(a.y), "f"(a.z), "f"(a.w),
           "f"(b.x), "f"(b.y), "f"(b.z), "f"(b.w)
        : "memory");
}

__global__ void __launch_bounds__(256)
cplstm_tma_kernel(const float4* __restrict__ dec_b4,
                  float* __restrict__ out,
                  int V4,        // float4 columns per row (8000)
                  int rows,      // S*B (4096)
                  int chunk,     // rows per CTA (8)
                  int nseg,      // column segments per row (4)
                  int segF4,     // float4 per segment (2000 = 32000 B)
                  int n_main,    // main CTAs (nseg * rows/chunk)
                  size_t tail_off,   // float offset of state tail
                  size_t tail_n8)    // 32B chunks in state tail
{
    extern __shared__ float4 sbuf[];
    const int cid = blockIdx.x;

    if (cid < n_main) {
        const int seg = cid % nseg;
        const int yc  = cid / nseg;

        // Stage this CTA's dec_b column segment into SMEM (once; L2-resident).
        const float4* src = dec_b4 + (size_t)seg * segF4;
        for (int i = threadIdx.x; i < segF4; i += 256)
            sbuf[i] = __ldg(src + i);
        __syncthreads();

        if (threadIdx.x == 0) {
            // Make generic-proxy SMEM writes visible to the async proxy.
            asm volatile("fence.proxy.async.shared::cta;" ::: "memory");

            uint32_t saddr = (uint32_t)__cvta_generic_to_shared(sbuf);
            const unsigned bytes = (unsigned)segF4 * 16u;   // 32000

            int r0   = yc * chunk;
            int rend = r0 + chunk; if (rend > rows) rend = rows;

            const size_t rowF = (size_t)V4 * 4;             // floats per row
            float* dst = out + (size_t)r0 * rowF + (size_t)seg * segF4 * 4;

            for (int r = r0; r < rend; ++r) {
                asm volatile(
                    "cp.async.bulk.global.shared::cta.bulk_group [%0], [%1], %2;"
                    :: "l"(dst), "r"(saddr), "r"(bytes) : "memory");
                dst += rowF;
            }
            asm volatile("cp.async.bulk.commit_group;" ::: "memory");
            asm volatile("cp.async.bulk.wait_group 0;" ::: "memory");
        }
        // other threads exit; issuing thread holds the CTA until drain
    } else {
        // Tail CTAs zero the 256 KB (c_T, h_T) state outputs.
        const int t = cid - n_main;
        const int tail_blocks = gridDim.x - n_main;
        const size_t stride = (size_t)tail_blocks * 256;
        const float4 z = make_float4(0.f, 0.f, 0.f, 0.f);
        for (size_t i = (size_t)t * 256 + threadIdx.x; i < tail_n8; i += stride)
            st_v8(out + tail_off + i * 8, z, z);
    }
}

// Defensive generic path (only for odd sizes — not this problem's shapes).
__global__ void cplstm_generic_kernel(const float* __restrict__ dec_b,
                                      float* __restrict__ out,
                                      size_t n_total, size_t n_logits, int V)
{
    size_t i = (size_t)blockIdx.x * blockDim.x + threadIdx.x;
    const size_t stride = (size_t)gridDim.x * blockDim.x;
    for (; i < n_total; i += stride) {
        float s = (i < n_logits) ? dec_b[i % (size_t)V] : 0.f;
        out[i] = s;
    }
}

extern "C" void kernel_launch(void* const* d_in, const int* in_sizes, int n_in,
                              void* d_out, int out_size)
{
    // metadata order: inp(S,B) int32, emb(V,D), a(H,4R), b(D,4R), ct(4R,H),
    //                 dec_w(V,H), dec_b(V,)
    const float* dec_b = (const float*)d_in[6];
    float*       out   = (float*)d_out;

    const size_t SB = (size_t)in_sizes[0];   // S*B = 4096 rows
    const int    V  = in_sizes[6];           // 32000
    const size_t n_total = (size_t)out_size;
    size_t n_logits = SB * (size_t)V;
    if (n_logits > n_total) n_logits = n_total;

    const size_t n_tail = n_total - n_logits;

    const int nseg  = 4;
    const int chunk = 8;
    const int V4    = V >> 2;                // 8000

    // TMA path needs V divisible by 16 (16B-aligned segment boundaries:
    // V4 % nseg == 0 and segment bytes % 16 == 0) and 32B-aligned tail.
    if ((V & 15) != 0 || (V4 % nseg) != 0 || (n_logits & 7) != 0 ||
        (n_tail & 7) != 0 || (SB % chunk) != 0) {
        cplstm_generic_kernel<<<148 * 8, 256>>>(dec_b, out, n_total, n_logits, V);
        return;
    }

    const int rows   = (int)SB;              // 4096
    const int segF4  = V4 / nseg;            // 2000 float4 = 32000 B (< 48KB smem)
    const int n_main = nseg * (rows / chunk);// 4 * 512 = 2048 CTAs
    const int tail_blocks = (n_tail > 0) ? 8 : 0;

    const size_t smem_bytes = (size_t)segF4 * 16;  // 32000 B

    cplstm_tma_kernel<<<n_main + tail_blocks, 256, smem_bytes>>>(
        (const float4*)dec_b, out, V4, rows, chunk, nseg, segF4, n_main,
        n_logits, n_tail >> 3);
}

// round 13
// speedup vs baseline: 1.1318x; 1.1318x over previous
#include <cuda_runtime.h>
#include <cuda_bf16.h>
#include <cstdint>

// CPLSTM_20959440405049 — FINAL. Constant-folded solution.
//
// Proof: h0=0 and the multiplicative gate g=(h@a)*(x_t@b) give g=0 ==>
// f=i=o=sigmoid(0)=0.5, g_t=tanh(0)=0 ==> c'=0.5*0+0.5*0=0, h'=0.5*tanh(0)=0;
// by induction h_t=c_t=0 exactly for all 128 steps (exact zeros, no rounding).
// Hence output = dec_b broadcast over (S*B, V); (c_T, h_T) = zeros.
// rel_err measured 0.0 across all rounds.
//
// Optimization history: six store mechanisms probed (v4 interleaved / v4
// chunk-8 / full-row+reload / v8 .cs / v8 write-back / TMA bulk). Four
// register-resident configs converge at 6.44-6.50 TB/s with issue<10%,
// L2<62%, occ>82% — the HBM write-path ceiling (~81% of 8 TB/s aggregate
// spec; pure-write streams pay turnaround overhead). This kernel is the
// measured best: register-resident v8 stores, contiguous 4-row chunks,
// 16384 CTAs, fused state-tail zeroing. 73.76 us wallclock / 72.2 us kernel.

__device__ __forceinline__ void st_v8(float* p, const float4& a, const float4& b)
{
    asm volatile(
        "st.global.v8.f32 [%0], {%1,%2,%3,%4,%5,%6,%7,%8};"
        :: "l"(p),
           "f"(a.x), "f"(a.y), "f"(a.z), "f"(a.w),
           "f"(b.x), "f"(b.y), "f"(b.z), "f"(b.w)
        : "memory");
}

__global__ void __launch_bounds__(256)
cplstm_v8_kernel(const float4* __restrict__ dec_b4,
                 float* __restrict__ out,
                 int V8,            // V/8 32-byte columns per row
                 int rows,          // S*B rows
                 int chunk,         // contiguous rows per CTA-y
                 size_t tail_off,   // float offset of state tail
                 size_t tail_n8)    // 32-byte chunks in state tail
{
    const int col8 = blockIdx.x * blockDim.x + threadIdx.x;

    if (col8 < V8) {
        // Value loaded ONCE, register-resident (two float4 = one 32B chunk).
        const float4 v0 = __ldg(dec_b4 + 2 * col8);
        const float4 v1 = __ldg(dec_b4 + 2 * col8 + 1);

        const int r0 = blockIdx.y * chunk;
        int rend = r0 + chunk;
        if (rend > rows) rend = rows;

        const size_t rowf = (size_t)V8 * 8;          // floats per row
        float* p = out + (size_t)r0 * rowf + (size_t)col8 * 8;
        #pragma unroll 4
        for (int r = r0; r < rend; ++r) {
            st_v8(p, v0, v1);        // 256-bit store; steady state STG+IADD only
            p += rowf;               // +32 KB (page-local 128 KB window)
        }
    } else {
        // Overshoot threads zero the 256 KB (c_T, h_T) tail in parallel.
        const int over = gridDim.x * blockDim.x - V8;
        size_t i = (size_t)(col8 - V8) + (size_t)over * blockIdx.y;
        const size_t stride = (size_t)over * gridDim.y;
        const float4 z = make_float4(0.f, 0.f, 0.f, 0.f);
        for (; i < tail_n8; i += stride)
            st_v8(out + tail_off + i * 8, z, z);
    }
}

// Defensive generic path (only for odd sizes — not this problem's shapes).
__global__ void cplstm_generic_kernel(const float* __restrict__ dec_b,
                                      float* __restrict__ out,
                                      size_t n_total, size_t n_logits, int V)
{
    size_t i = (size_t)blockIdx.x * blockDim.x + threadIdx.x;
    const size_t stride = (size_t)gridDim.x * blockDim.x;
    for (; i < n_total; i += stride) {
        float s = (i < n_logits) ? dec_b[i % (size_t)V] : 0.f;
        out[i] = s;
    }
}

extern "C" void kernel_launch(void* const* d_in, const int* in_sizes, int n_in,
                              void* d_out, int out_size)
{
    // metadata order: inp(S,B) int32, emb(V,D), a(H,4R), b(D,4R), ct(4R,H),
    //                 dec_w(V,H), dec_b(V,)
    const float* dec_b = (const float*)d_in[6];
    float*       out   = (float*)d_out;

    const size_t SB = (size_t)in_sizes[0];   // S*B = 4096 rows
    const int    V  = in_sizes[6];           // 32000
    const size_t n_total = (size_t)out_size;
    size_t n_logits = SB * (size_t)V;
    if (n_logits > n_total) n_logits = n_total;

    const size_t n_tail = n_total - n_logits;

    // v8 path needs: V % 8 == 0, logits offset and tail both 32B-multiples.
    if ((V & 7) != 0 || (n_logits & 7) != 0 || (n_tail & 7) != 0) {
        cplstm_generic_kernel<<<148 * 8, 256>>>(dec_b, out, n_total, n_logits, V);
        return;
    }

    const int V8   = V >> 3;                 // 4000 32B columns per row
    const int rows = (int)SB;                // 4096

    // grid.x = 16 col blocks (4096 slots >= 4000; 96 overshoot threads per
    // row-tile zero the tail). gy = 1024, chunk = 4 -> 16384 CTAs (the
    // measured stream-count plateau), 4 independent 256-bit stores/thread.
    dim3 block(256, 1, 1);
    int gy = 1024;
    if (gy > rows) gy = rows;
    const int chunk = (rows + gy - 1) / gy;  // 4
    dim3 grid((V8 + 255) / 256, gy, 1);

    if ((int)grid.x * 256 == V8 && n_tail > 0) grid.x += 1;

    cplstm_v8_kernel<<<grid, block>>>(
        (const float4*)dec_b, out, V8, rows, chunk,
        n_logits, n_tail >> 3);
}